// round 9
// baseline (speedup 1.0000x reference)
#include <cuda_runtime.h>
#include <cstdint>

// FP32->FP16 gate-level emulation, collapsed to integer logic. v8:
//   - 256-bit global loads/stores (Blackwell ld/st.global.v8.b32).
//   - L2 prefetch-ahead at 192 tiles (768KB) lead: each warp prefetches the
//     full 4KB tile of the warp 192 ahead with ONE prefetch.global.L2
//     (lane l -> line l), turning demand DRAM misses into L2 hits.
//   - PRMT/multiply bit-pack, 2-step shfl_xor OR-butterfly transpose.
//   - integer fp32->fp16 RNE conversion (bit-exact vs gate algebra on {0,1}).
//   - branch-free bit->float, streaming cache hints, 512-thread blocks.

#define PF_DIST 192   // prefetch distance, in 32-row tiles (= warps)

__device__ __forceinline__ void ldg256(const float* __restrict__ p, unsigned r[8]) {
    asm volatile(
        "ld.global.cs.v8.b32 {%0,%1,%2,%3,%4,%5,%6,%7}, [%8];"
        : "=r"(r[0]), "=r"(r[1]), "=r"(r[2]), "=r"(r[3]),
          "=r"(r[4]), "=r"(r[5]), "=r"(r[6]), "=r"(r[7])
        : "l"(p));
}

__device__ __forceinline__ void stg256(float* __restrict__ p, const unsigned r[8]) {
    asm volatile(
        "st.global.cs.v8.b32 [%0], {%1,%2,%3,%4,%5,%6,%7,%8};"
        :: "l"(p),
           "r"(r[0]), "r"(r[1]), "r"(r[2]), "r"(r[3]),
           "r"(r[4]), "r"(r[5]), "r"(r[6]), "r"(r[7])
        : "memory");
}

__device__ __forceinline__ unsigned convert_row(unsigned w) {
    unsigned s = w >> 31;
    unsigned e = (w >> 23) & 0xFFu;
    unsigned m = w & 0x7FFFFFu;

    unsigned h;
    if (e == 255u) {
        h = (s << 15) | (m ? 0x7E00u : 0x7C00u);       // nan / inf
    } else if (e < 113u) {
        h = 0u;                                         // underflow -> +0
    } else if (e > 142u) {
        h = (s << 15) | 0x7C00u;                        // overflow -> inf
    } else {
        unsigned mant10 = m >> 13;
        unsigned L = mant10 & 1u;
        unsigned R = (m >> 12) & 1u;
        unsigned S = (m & 0xFFFu) != 0u;
        unsigned round_up = R & (S | L);
        unsigned mant_r = mant10 + round_up;            // 11-bit
        unsigned carry = mant_r >> 10;
        unsigned mant_f = mant_r & 0x3FFu;
        unsigned exp5 = (e - 112u + carry) & 31u;       // 5-bit wrap add
        h = (s << 15) | (exp5 << 10) | mant_f;
    }
    return h;
}

// Gather the 8 "bit" floats of one 256-bit chunk into a byte:
// bit f of result = (r[f] != 0), via byte3 of 0x3F800000 (= 0x3F, bit0 set).
__device__ __forceinline__ unsigned pack8(const unsigned r[8]) {
    unsigned p0 = __byte_perm(r[0], r[1], 0x0073);
    unsigned p1 = __byte_perm(r[2], r[3], 0x0073);
    unsigned blo = __byte_perm(p0, p1, 0x5410);        // {b3 of r0..r3}
    unsigned p2 = __byte_perm(r[4], r[5], 0x0073);
    unsigned p3 = __byte_perm(r[6], r[7], 0x0073);
    unsigned bhi = __byte_perm(p2, p3, 0x5410);        // {b3 of r4..r7}
    unsigned nlo = ((blo & 0x01010101u) * 0x01020408u) >> 24;
    unsigned nhi = ((bhi & 0x01010101u) * 0x01020408u) >> 24;
    return nlo | (nhi << 4);
}

__global__ void __launch_bounds__(512)
fp32_to_fp16_bits_kernel(const float* __restrict__ in,
                         float* __restrict__ out,
                         int nrows) {
    const int lane = threadIdx.x & 31;
    const int warpId = (int)((blockIdx.x * blockDim.x + threadIdx.x) >> 5);
    const int rowbase = warpId * 32;                   // 32 rows per warp
    if (__builtin_expect(rowbase >= nrows, 0)) return;

    const float* ip = in + (size_t)rowbase * 32;       // 1024 floats = 4KB tile

    // ---- L2 prefetch: full 4KB tile PF_DIST warps ahead, one instruction ----
    if (rowbase + PF_DIST * 32 < nrows) {
        const float* pf = ip + (size_t)PF_DIST * 1024 + (size_t)lane * 32;
        asm volatile("prefetch.global.L2 [%0];" :: "l"(pf));
    }

    // ---- input: 4 x 256-bit coalesced loads per warp (front-batched) ----
    unsigned v[4][8];
#pragma unroll
    for (int i = 0; i < 4; i++)
        ldg256(ip + ((size_t)i * 32 + lane) * 8, v[i]);

    // ---- transpose: assemble pulse-order uint32 word per row ----
    // load i, lane l holds row i*8 + (l>>2), quarter q = l&3 (pulses 8q..8q+7)
    const unsigned q8 = (lane & 3) * 8;
    unsigned myword = 0u;
#pragma unroll
    for (int i = 0; i < 4; i++) {
        unsigned word = pack8(v[i]) << q8;
        // OR across the 4 lanes sharing a row
        word |= __shfl_xor_sync(0xFFFFFFFFu, word, 1);
        word |= __shfl_xor_sync(0xFFFFFFFFu, word, 2);
        // row i*8+k replicated in lanes 4k..4k+3; lane l wants row l
        unsigned tmp = __shfl_sync(0xFFFFFFFFu, word, 4 * (lane & 7));
        if ((lane >> 3) == i) myword = tmp;
    }
    unsigned w = __brev(myword);   // pulse order -> IEEE layout (pulse0 = bit31)

    // ---- compute ----
    unsigned h = convert_row(w);

    // ---- output: 2 x 256-bit coalesced stores per warp ----
    // store j, lane l covers row j*16 + (l>>1), half hh = l&1 (8 floats)
    float* op = out + (size_t)rowbase * 16;            // 512 floats = 64 chunks
    const int hh8 = (lane & 1) * 8;
#pragma unroll
    for (int j = 0; j < 2; j++) {
        unsigned hr = __shfl_sync(0xFFFFFFFFu, h, j * 16 + (lane >> 1));
        unsigned u = hr << (16 + hh8);                 // first float's bit -> 31
        unsigned f[8];
#pragma unroll
        for (int k = 0; k < 8; k++)
            f[k] = ((unsigned)((int)(u << k) >> 31)) & 0x3F800000u;
        stg256(op + ((size_t)j * 32 + lane) * 8, f);
    }
}

extern "C" void kernel_launch(void* const* d_in, const int* in_sizes, int n_in,
                              void* d_out, int out_size) {
    const float* in = (const float*)d_in[0];
    float* out = (float*)d_out;

    int nrows = in_sizes[0] / 32;            // 2048*1024 = 2097152
    int nwarps = (nrows + 31) / 32;          // one warp per 32 rows
    int threads = 512;                       // 16 warps per block
    int blocks = (nwarps + 15) / 16;         // 4096 blocks

    fp32_to_fp16_bits_kernel<<<blocks, threads>>>(in, out, nrows);
}

// round 10
// speedup vs baseline: 1.0078x; 1.0078x over previous
#include <cuda_runtime.h>
#include <cstdint>

// FP32->FP16 gate-level emulation, collapsed to integer logic. v9 (= v7, final):
//   - 256-bit global loads/stores (Blackwell ld/st.global.v8.b32).
//   - L2 prefetch-ahead at 64 tiles (256KB) lead — measured optimum
//     (192 tiles regressed: L2 thrash + L1tex prefetch replays).
//   - PRMT/multiply bit-pack, 2-step shfl_xor OR-butterfly transpose.
//   - integer fp32->fp16 RNE conversion (bit-exact vs gate algebra on {0,1}).
//   - branch-free bit->float, streaming cache hints, 256-thread blocks.
// Kernel is at the HBM ceiling for a 2:1 R/W mix (~6.6 TB/s, 83% DRAM duty).

#define PF_DIST 64   // prefetch distance, in 32-row tiles (= warps)

__device__ __forceinline__ void ldg256(const float* __restrict__ p, unsigned r[8]) {
    asm volatile(
        "ld.global.cs.v8.b32 {%0,%1,%2,%3,%4,%5,%6,%7}, [%8];"
        : "=r"(r[0]), "=r"(r[1]), "=r"(r[2]), "=r"(r[3]),
          "=r"(r[4]), "=r"(r[5]), "=r"(r[6]), "=r"(r[7])
        : "l"(p));
}

__device__ __forceinline__ void stg256(float* __restrict__ p, const unsigned r[8]) {
    asm volatile(
        "st.global.cs.v8.b32 [%0], {%1,%2,%3,%4,%5,%6,%7,%8};"
        :: "l"(p),
           "r"(r[0]), "r"(r[1]), "r"(r[2]), "r"(r[3]),
           "r"(r[4]), "r"(r[5]), "r"(r[6]), "r"(r[7])
        : "memory");
}

__device__ __forceinline__ unsigned convert_row(unsigned w) {
    unsigned s = w >> 31;
    unsigned e = (w >> 23) & 0xFFu;
    unsigned m = w & 0x7FFFFFu;

    unsigned h;
    if (e == 255u) {
        h = (s << 15) | (m ? 0x7E00u : 0x7C00u);       // nan / inf
    } else if (e < 113u) {
        h = 0u;                                         // underflow -> +0
    } else if (e > 142u) {
        h = (s << 15) | 0x7C00u;                        // overflow -> inf
    } else {
        unsigned mant10 = m >> 13;
        unsigned L = mant10 & 1u;
        unsigned R = (m >> 12) & 1u;
        unsigned S = (m & 0xFFFu) != 0u;
        unsigned round_up = R & (S | L);
        unsigned mant_r = mant10 + round_up;            // 11-bit
        unsigned carry = mant_r >> 10;
        unsigned mant_f = mant_r & 0x3FFu;
        unsigned exp5 = (e - 112u + carry) & 31u;       // 5-bit wrap add
        h = (s << 15) | (exp5 << 10) | mant_f;
    }
    return h;
}

// Gather the 8 "bit" floats of one 256-bit chunk into a byte:
// bit f of result = (r[f] != 0), via byte3 of 0x3F800000 (= 0x3F, bit0 set).
__device__ __forceinline__ unsigned pack8(const unsigned r[8]) {
    unsigned p0 = __byte_perm(r[0], r[1], 0x0073);
    unsigned p1 = __byte_perm(r[2], r[3], 0x0073);
    unsigned blo = __byte_perm(p0, p1, 0x5410);        // {b3 of r0..r3}
    unsigned p2 = __byte_perm(r[4], r[5], 0x0073);
    unsigned p3 = __byte_perm(r[6], r[7], 0x0073);
    unsigned bhi = __byte_perm(p2, p3, 0x5410);        // {b3 of r4..r7}
    unsigned nlo = ((blo & 0x01010101u) * 0x01020408u) >> 24;
    unsigned nhi = ((bhi & 0x01010101u) * 0x01020408u) >> 24;
    return nlo | (nhi << 4);
}

__global__ void __launch_bounds__(256)
fp32_to_fp16_bits_kernel(const float* __restrict__ in,
                         float* __restrict__ out,
                         int nrows) {
    const int lane = threadIdx.x & 31;
    const int warpId = (int)((blockIdx.x * blockDim.x + threadIdx.x) >> 5);
    const int rowbase = warpId * 32;                   // 32 rows per warp
    if (__builtin_expect(rowbase >= nrows, 0)) return;

    const float* ip = in + (size_t)rowbase * 32;       // 1024 floats = 4KB tile

    // ---- L2 prefetch: full 4KB tile PF_DIST warps ahead, one instruction ----
    if (rowbase + PF_DIST * 32 < nrows) {
        const float* pf = ip + (size_t)PF_DIST * 1024 + (size_t)lane * 32;
        asm volatile("prefetch.global.L2 [%0];" :: "l"(pf));
    }

    // ---- input: 4 x 256-bit coalesced loads per warp (front-batched) ----
    unsigned v[4][8];
#pragma unroll
    for (int i = 0; i < 4; i++)
        ldg256(ip + ((size_t)i * 32 + lane) * 8, v[i]);

    // ---- transpose: assemble pulse-order uint32 word per row ----
    // load i, lane l holds row i*8 + (l>>2), quarter q = l&3 (pulses 8q..8q+7)
    const unsigned q8 = (lane & 3) * 8;
    unsigned myword = 0u;
#pragma unroll
    for (int i = 0; i < 4; i++) {
        unsigned word = pack8(v[i]) << q8;
        // OR across the 4 lanes sharing a row
        word |= __shfl_xor_sync(0xFFFFFFFFu, word, 1);
        word |= __shfl_xor_sync(0xFFFFFFFFu, word, 2);
        // row i*8+k replicated in lanes 4k..4k+3; lane l wants row l
        unsigned tmp = __shfl_sync(0xFFFFFFFFu, word, 4 * (lane & 7));
        if ((lane >> 3) == i) myword = tmp;
    }
    unsigned w = __brev(myword);   // pulse order -> IEEE layout (pulse0 = bit31)

    // ---- compute ----
    unsigned h = convert_row(w);

    // ---- output: 2 x 256-bit coalesced stores per warp ----
    // store j, lane l covers row j*16 + (l>>1), half hh = l&1 (8 floats)
    float* op = out + (size_t)rowbase * 16;            // 512 floats = 64 chunks
    const int hh8 = (lane & 1) * 8;
#pragma unroll
    for (int j = 0; j < 2; j++) {
        unsigned hr = __shfl_sync(0xFFFFFFFFu, h, j * 16 + (lane >> 1));
        unsigned u = hr << (16 + hh8);                 // first float's bit -> 31
        unsigned f[8];
#pragma unroll
        for (int k = 0; k < 8; k++)
            f[k] = ((unsigned)((int)(u << k) >> 31)) & 0x3F800000u;
        stg256(op + ((size_t)j * 32 + lane) * 8, f);
    }
}

extern "C" void kernel_launch(void* const* d_in, const int* in_sizes, int n_in,
                              void* d_out, int out_size) {
    const float* in = (const float*)d_in[0];
    float* out = (float*)d_out;

    int nrows = in_sizes[0] / 32;            // 2048*1024 = 2097152
    int nwarps = (nrows + 31) / 32;          // one warp per 32 rows
    int threads = 256;                       // 8 warps per block
    int blocks = (nwarps + 7) / 8;           // 8192 blocks

    fp32_to_fp16_bits_kernel<<<blocks, threads>>>(in, out, nrows);
}

// round 11
// speedup vs baseline: 1.0083x; 1.0005x over previous
#include <cuda_runtime.h>
#include <cstdint>

// FP32->FP16 gate-level emulation, collapsed to integer logic. v10:
//   identical to v9 except PF_DIST 64 -> 96 (single-parameter probe of the
//   prefetch-distance optimum; response curve so far: 0->53.6us, 64->52.6us,
//   192->60.9us cliff).
//   - 256-bit global loads/stores (Blackwell ld/st.global.v8.b32).
//   - L2 prefetch-ahead: one prefetch.global.L2 per warp covers a full 4KB
//     tile (lane l -> line l) PF_DIST warps ahead.
//   - PRMT/multiply bit-pack, 2-step shfl_xor OR-butterfly transpose.
//   - integer fp32->fp16 RNE conversion (bit-exact vs gate algebra on {0,1}).
//   - branch-free bit->float, streaming cache hints, 256-thread blocks.

#define PF_DIST 96   // prefetch distance, in 32-row tiles (= warps)

__device__ __forceinline__ void ldg256(const float* __restrict__ p, unsigned r[8]) {
    asm volatile(
        "ld.global.cs.v8.b32 {%0,%1,%2,%3,%4,%5,%6,%7}, [%8];"
        : "=r"(r[0]), "=r"(r[1]), "=r"(r[2]), "=r"(r[3]),
          "=r"(r[4]), "=r"(r[5]), "=r"(r[6]), "=r"(r[7])
        : "l"(p));
}

__device__ __forceinline__ void stg256(float* __restrict__ p, const unsigned r[8]) {
    asm volatile(
        "st.global.cs.v8.b32 [%0], {%1,%2,%3,%4,%5,%6,%7,%8};"
        :: "l"(p),
           "r"(r[0]), "r"(r[1]), "r"(r[2]), "r"(r[3]),
           "r"(r[4]), "r"(r[5]), "r"(r[6]), "r"(r[7])
        : "memory");
}

__device__ __forceinline__ unsigned convert_row(unsigned w) {
    unsigned s = w >> 31;
    unsigned e = (w >> 23) & 0xFFu;
    unsigned m = w & 0x7FFFFFu;

    unsigned h;
    if (e == 255u) {
        h = (s << 15) | (m ? 0x7E00u : 0x7C00u);       // nan / inf
    } else if (e < 113u) {
        h = 0u;                                         // underflow -> +0
    } else if (e > 142u) {
        h = (s << 15) | 0x7C00u;                        // overflow -> inf
    } else {
        unsigned mant10 = m >> 13;
        unsigned L = mant10 & 1u;
        unsigned R = (m >> 12) & 1u;
        unsigned S = (m & 0xFFFu) != 0u;
        unsigned round_up = R & (S | L);
        unsigned mant_r = mant10 + round_up;            // 11-bit
        unsigned carry = mant_r >> 10;
        unsigned mant_f = mant_r & 0x3FFu;
        unsigned exp5 = (e - 112u + carry) & 31u;       // 5-bit wrap add
        h = (s << 15) | (exp5 << 10) | mant_f;
    }
    return h;
}

// Gather the 8 "bit" floats of one 256-bit chunk into a byte:
// bit f of result = (r[f] != 0), via byte3 of 0x3F800000 (= 0x3F, bit0 set).
__device__ __forceinline__ unsigned pack8(const unsigned r[8]) {
    unsigned p0 = __byte_perm(r[0], r[1], 0x0073);
    unsigned p1 = __byte_perm(r[2], r[3], 0x0073);
    unsigned blo = __byte_perm(p0, p1, 0x5410);        // {b3 of r0..r3}
    unsigned p2 = __byte_perm(r[4], r[5], 0x0073);
    unsigned p3 = __byte_perm(r[6], r[7], 0x0073);
    unsigned bhi = __byte_perm(p2, p3, 0x5410);        // {b3 of r4..r7}
    unsigned nlo = ((blo & 0x01010101u) * 0x01020408u) >> 24;
    unsigned nhi = ((bhi & 0x01010101u) * 0x01020408u) >> 24;
    return nlo | (nhi << 4);
}

__global__ void __launch_bounds__(256)
fp32_to_fp16_bits_kernel(const float* __restrict__ in,
                         float* __restrict__ out,
                         int nrows) {
    const int lane = threadIdx.x & 31;
    const int warpId = (int)((blockIdx.x * blockDim.x + threadIdx.x) >> 5);
    const int rowbase = warpId * 32;                   // 32 rows per warp
    if (__builtin_expect(rowbase >= nrows, 0)) return;

    const float* ip = in + (size_t)rowbase * 32;       // 1024 floats = 4KB tile

    // ---- L2 prefetch: full 4KB tile PF_DIST warps ahead, one instruction ----
    if (rowbase + PF_DIST * 32 < nrows) {
        const float* pf = ip + (size_t)PF_DIST * 1024 + (size_t)lane * 32;
        asm volatile("prefetch.global.L2 [%0];" :: "l"(pf));
    }

    // ---- input: 4 x 256-bit coalesced loads per warp (front-batched) ----
    unsigned v[4][8];
#pragma unroll
    for (int i = 0; i < 4; i++)
        ldg256(ip + ((size_t)i * 32 + lane) * 8, v[i]);

    // ---- transpose: assemble pulse-order uint32 word per row ----
    // load i, lane l holds row i*8 + (l>>2), quarter q = l&3 (pulses 8q..8q+7)
    const unsigned q8 = (lane & 3) * 8;
    unsigned myword = 0u;
#pragma unroll
    for (int i = 0; i < 4; i++) {
        unsigned word = pack8(v[i]) << q8;
        // OR across the 4 lanes sharing a row
        word |= __shfl_xor_sync(0xFFFFFFFFu, word, 1);
        word |= __shfl_xor_sync(0xFFFFFFFFu, word, 2);
        // row i*8+k replicated in lanes 4k..4k+3; lane l wants row l
        unsigned tmp = __shfl_sync(0xFFFFFFFFu, word, 4 * (lane & 7));
        if ((lane >> 3) == i) myword = tmp;
    }
    unsigned w = __brev(myword);   // pulse order -> IEEE layout (pulse0 = bit31)

    // ---- compute ----
    unsigned h = convert_row(w);

    // ---- output: 2 x 256-bit coalesced stores per warp ----
    // store j, lane l covers row j*16 + (l>>1), half hh = l&1 (8 floats)
    float* op = out + (size_t)rowbase * 16;            // 512 floats = 64 chunks
    const int hh8 = (lane & 1) * 8;
#pragma unroll
    for (int j = 0; j < 2; j++) {
        unsigned hr = __shfl_sync(0xFFFFFFFFu, h, j * 16 + (lane >> 1));
        unsigned u = hr << (16 + hh8);                 // first float's bit -> 31
        unsigned f[8];
#pragma unroll
        for (int k = 0; k < 8; k++)
            f[k] = ((unsigned)((int)(u << k) >> 31)) & 0x3F800000u;
        stg256(op + ((size_t)j * 32 + lane) * 8, f);
    }
}

extern "C" void kernel_launch(void* const* d_in, const int* in_sizes, int n_in,
                              void* d_out, int out_size) {
    const float* in = (const float*)d_in[0];
    float* out = (float*)d_out;

    int nrows = in_sizes[0] / 32;            // 2048*1024 = 2097152
    int nwarps = (nrows + 31) / 32;          // one warp per 32 rows
    int threads = 256;                       // 8 warps per block
    int blocks = (nwarps + 7) / 8;           // 8192 blocks

    fp32_to_fp16_bits_kernel<<<blocks, threads>>>(in, out, nrows);
}